// round 1
// baseline (speedup 1.0000x reference)
#include <cuda_runtime.h>
#include <cuda_bf16.h>
#include <math.h>

// ---------------------------------------------------------------------------
// MixerGatedDeltaNet: proj GEMM -> causal depthwise conv4 + SiLU -> l2norm ->
// gated delta-rule scan -> output gate.
// B=2, L=2048, D_MODEL=2048, N_HEADS=16, D_HEAD=128, HEAD_V=256
// ---------------------------------------------------------------------------

#define B_SZ   2
#define L_SEQ  2048
#define DM     2048
#define NPROJ  12320          // q(2048) k(2048) v(4096) gate(4096) b(16) A(16)
#define CQKV   8192
#define NH     16
#define DH     128
#define HV     256
#define KEYD   2048
#define VALD   4096
#define GM     4096           // B*L
#define GK     2048
#define GN     12320

// Scratch (device globals: allocation-free rule)
static __device__ float g_proj[B_SZ * L_SEQ * NPROJ];   // 202 MB
static __device__ float g_qkv [B_SZ * L_SEQ * CQKV];    // 134 MB (post conv/silu/norm)
static __device__ float g_dec [B_SZ * L_SEQ * NH];      // exp(g) decay
static __device__ float g_beta[B_SZ * L_SEQ * NH];

// ---------------------------------------------------------------------------
// K1: fp32 SGEMM  g_proj[4096,12320] = hidden[4096,2048] @ W[2048,12320]
// Classic 128x128x8 tile, 256 threads, 8x8 microtile.
// ---------------------------------------------------------------------------
__global__ __launch_bounds__(256) void gemm_kernel(const float* __restrict__ A,
                                                   const float* __restrict__ Bm)
{
    __shared__ float As[8][128];
    __shared__ float Bs[8][132];   // padded row

    const int tid = threadIdx.x;
    const int bx  = blockIdx.x;    // col tile (0..96)
    const int by  = blockIdx.y;    // row tile (0..31)
    const int tx  = tid & 15;
    const int ty  = tid >> 4;

    const int aRow = tid >> 1;            // 0..127
    const int aCol = (tid & 1) << 2;      // 0 or 4
    const int bRow = tid >> 5;            // 0..7
    const int bCol = (tid & 31) << 2;     // 0..124

    const float* Ab = A + (by * 128) * GK;
    const int colBase = bx * 128;

    float acc[8][8];
#pragma unroll
    for (int i = 0; i < 8; i++)
#pragma unroll
        for (int j = 0; j < 8; j++) acc[i][j] = 0.f;

    for (int k0 = 0; k0 < GK; k0 += 8) {
        // load A tile (M,K exact multiples: no guard)
        float4 a4 = *(const float4*)(Ab + aRow * GK + k0 + aCol);
        As[aCol + 0][aRow] = a4.x;
        As[aCol + 1][aRow] = a4.y;
        As[aCol + 2][aRow] = a4.z;
        As[aCol + 3][aRow] = a4.w;

        // load B tile with N guard
        int gc = colBase + bCol;
        const float* Bp = Bm + (k0 + bRow) * GN + gc;
        if (gc + 3 < GN) {
            float4 b4 = *(const float4*)Bp;
            Bs[bRow][bCol + 0] = b4.x;
            Bs[bRow][bCol + 1] = b4.y;
            Bs[bRow][bCol + 2] = b4.z;
            Bs[bRow][bCol + 3] = b4.w;
        } else {
            Bs[bRow][bCol + 0] = (gc + 0 < GN) ? Bp[0] : 0.f;
            Bs[bRow][bCol + 1] = (gc + 1 < GN) ? Bp[1] : 0.f;
            Bs[bRow][bCol + 2] = (gc + 2 < GN) ? Bp[2] : 0.f;
            Bs[bRow][bCol + 3] = (gc + 3 < GN) ? Bp[3] : 0.f;
        }
        __syncthreads();

#pragma unroll
        for (int kk = 0; kk < 8; kk++) {
            float4 a0 = *(const float4*)&As[kk][ty * 8];
            float4 a1 = *(const float4*)&As[kk][ty * 8 + 4];
            float4 b0 = *(const float4*)&Bs[kk][tx * 8];
            float4 b1 = *(const float4*)&Bs[kk][tx * 8 + 4];
            float ar[8] = {a0.x, a0.y, a0.z, a0.w, a1.x, a1.y, a1.z, a1.w};
            float br[8] = {b0.x, b0.y, b0.z, b0.w, b1.x, b1.y, b1.z, b1.w};
#pragma unroll
            for (int i = 0; i < 8; i++)
#pragma unroll
                for (int j = 0; j < 8; j++)
                    acc[i][j] += ar[i] * br[j];
        }
        __syncthreads();
    }

#pragma unroll
    for (int i = 0; i < 8; i++) {
        int row = by * 128 + ty * 8 + i;
#pragma unroll
        for (int j = 0; j < 8; j++) {
            int col = colBase + tx * 8 + j;
            if (col < GN) g_proj[row * GN + col] = acc[i][j];
        }
    }
}

// ---------------------------------------------------------------------------
// K2: causal depthwise conv (width 4) + SiLU over first 8192 proj channels.
// ---------------------------------------------------------------------------
__global__ __launch_bounds__(256) void conv_kernel(const float* __restrict__ Wc)
{
    int idx = blockIdx.x * 256 + threadIdx.x;           // over B*L*CQKV = 33.5M
    if (idx >= B_SZ * L_SEQ * CQKV) return;
    int c  = idx & (CQKV - 1);
    int bl = idx >> 13;
    int l  = bl & (L_SEQ - 1);

    const float* w = Wc + c * 4;
    float acc = 0.f;
#pragma unroll
    for (int j = 0; j < 4; j++) {
        int lp = l - 3 + j;
        if (lp >= 0) acc += g_proj[(bl - 3 + j) * NPROJ + c] * w[j];
    }
    acc = acc / (1.f + expf(-acc));    // SiLU
    g_qkv[idx] = acc;
}

// ---------------------------------------------------------------------------
// K3: l2norm q (with scale folded) and k, per (b,l,h). One warp each.
// ---------------------------------------------------------------------------
__global__ __launch_bounds__(256) void norm_kernel()
{
    int gw   = (blockIdx.x * 256 + threadIdx.x) >> 5;   // 0..65535
    int lane = threadIdx.x & 31;
    int h  = gw & (NH - 1);
    int bl = gw >> 4;

    float* qp = g_qkv + bl * CQKV + h * DH;
    float* kp = qp + KEYD;

    float4 q4 = ((float4*)qp)[lane];
    float4 k4 = ((float4*)kp)[lane];
    float sq = q4.x * q4.x + q4.y * q4.y + q4.z * q4.z + q4.w * q4.w;
    float sk = k4.x * k4.x + k4.y * k4.y + k4.z * k4.z + k4.w * k4.w;
#pragma unroll
    for (int m = 16; m; m >>= 1) {
        sq += __shfl_xor_sync(0xffffffffu, sq, m);
        sk += __shfl_xor_sync(0xffffffffu, sk, m);
    }
    float rq = rsqrtf(sq + 1e-6f) * 0.08838834764831845f;  // * D_HEAD^-0.5
    float rk = rsqrtf(sk + 1e-6f);
    q4.x *= rq; q4.y *= rq; q4.z *= rq; q4.w *= rq;
    k4.x *= rk; k4.y *= rk; k4.z *= rk; k4.w *= rk;
    ((float4*)qp)[lane] = q4;
    ((float4*)kp)[lane] = k4;
}

// ---------------------------------------------------------------------------
// K4: decay/beta prep per (b,l,h).
// ---------------------------------------------------------------------------
__global__ __launch_bounds__(256) void gb_kernel(const float* __restrict__ A_log,
                                                 const float* __restrict__ dt_bias)
{
    int idx = blockIdx.x * 256 + threadIdx.x;
    if (idx >= B_SZ * L_SEQ * NH) return;
    int h  = idx & (NH - 1);
    int bl = idx >> 4;
    const float* pr = g_proj + bl * NPROJ;
    float bv = pr[12288 + h];
    float av = pr[12304 + h];
    float beta = 1.f / (1.f + expf(-bv));
    float x  = av + dt_bias[h];
    float sp = (x > 20.f) ? x : log1pf(expf(x));
    float g  = -expf(A_log[h]) * sp;
    g_dec[idx]  = expf(g);
    g_beta[idx] = beta;
}

// ---------------------------------------------------------------------------
// K5: gated delta-rule scan. grid = 32 (b,h) x 4 v-blocks = 128 CTAs.
// 256 threads; thread (kseg = tid&3, vloc = tid>>2) owns S[kseg*32..+31, vloc].
// kv/o reduced across the 4-lane kseg group via shfl.xor.
// ---------------------------------------------------------------------------
#define CHUNK 64
#define SK_ROW 144   // 4 segments x 36 (16B-aligned, conflict-free)

__global__ __launch_bounds__(256) void scan_kernel(float* __restrict__ out)
{
    extern __shared__ float smem[];
    float* sk    = smem;                       // 64*144
    float* sq    = sk + CHUNK * SK_ROW;        // 64*144
    float* sv    = sq + CHUNK * SK_ROW;        // 64*64
    float* sga   = sv + CHUNK * 64;            // 64*64
    float* sdec  = sga + CHUNK * 64;           // 64
    float* sbeta = sdec + CHUNK;               // 64

    const int tid   = threadIdx.x;
    const int vblk  = blockIdx.x & 3;
    const int bh    = blockIdx.x >> 2;
    const int b     = bh >> 4;
    const int h     = bh & 15;
    const int kseg  = tid & 3;
    const int vloc  = tid >> 2;
    const int vbase = vblk * 64;
    const int blb   = b * L_SEQ;

    float S[32];
#pragma unroll
    for (int i = 0; i < 32; i++) S[i] = 0.f;

    for (int t0 = 0; t0 < L_SEQ; t0 += CHUNK) {
        __syncthreads();
        // stage q,k (seg-padded layout), v, gate, decay, beta
        for (int j = tid; j < CHUNK * DH; j += 256) {
            int s = j >> 7, d = j & 127;
            int row = (blb + t0 + s) * CQKV + h * DH;
            int si  = s * SK_ROW + (d >> 5) * 36 + (d & 31);
            sq[si] = g_qkv[row + d];
            sk[si] = g_qkv[row + KEYD + d];
        }
        for (int j = tid; j < CHUNK * 64; j += 256) {
            int s = j >> 6, v = j & 63;
            int bl = blb + t0 + s;
            sv[j]  = g_qkv[bl * CQKV + 2 * KEYD + h * HV + vbase + v];
            sga[j] = g_proj[bl * NPROJ + CQKV + h * HV + vbase + v];
        }
        if (tid < CHUNK) {
            int bl = blb + t0 + tid;
            sdec[tid]  = g_dec[bl * NH + h];
            sbeta[tid] = g_beta[bl * NH + h];
        }
        __syncthreads();

        for (int s = 0; s < CHUNK; s++) {
            const float4* kp = (const float4*)&sk[s * SK_ROW + kseg * 36];
            const float4* qp = (const float4*)&sq[s * SK_ROW + kseg * 36];
            float kr[32], qr[32];
#pragma unroll
            for (int i = 0; i < 8; i++) {
                float4 t4 = kp[i];
                kr[4*i+0] = t4.x; kr[4*i+1] = t4.y; kr[4*i+2] = t4.z; kr[4*i+3] = t4.w;
                float4 u4 = qp[i];
                qr[4*i+0] = u4.x; qr[4*i+1] = u4.y; qr[4*i+2] = u4.z; qr[4*i+3] = u4.w;
            }
            float dec  = sdec[s];
            float beta = sbeta[s];

            // S *= dec ; kv = k . S (4 accumulators to break the FMA chain)
            float kv0 = 0.f, kv1 = 0.f, kv2 = 0.f, kv3 = 0.f;
#pragma unroll
            for (int i = 0; i < 32; i += 4) {
                S[i+0] *= dec; kv0 += kr[i+0] * S[i+0];
                S[i+1] *= dec; kv1 += kr[i+1] * S[i+1];
                S[i+2] *= dec; kv2 += kr[i+2] * S[i+2];
                S[i+3] *= dec; kv3 += kr[i+3] * S[i+3];
            }
            float kv = (kv0 + kv1) + (kv2 + kv3);
            kv += __shfl_xor_sync(0xffffffffu, kv, 1);
            kv += __shfl_xor_sync(0xffffffffu, kv, 2);

            float delta = (sv[s * 64 + vloc] - kv) * beta;

            float o0 = 0.f, o1 = 0.f, o2 = 0.f, o3 = 0.f;
#pragma unroll
            for (int i = 0; i < 32; i += 4) {
                S[i+0] += kr[i+0] * delta; o0 += qr[i+0] * S[i+0];
                S[i+1] += kr[i+1] * delta; o1 += qr[i+1] * S[i+1];
                S[i+2] += kr[i+2] * delta; o2 += qr[i+2] * S[i+2];
                S[i+3] += kr[i+3] * delta; o3 += qr[i+3] * S[i+3];
            }
            float o = (o0 + o1) + (o2 + o3);
            o += __shfl_xor_sync(0xffffffffu, o, 1);
            o += __shfl_xor_sync(0xffffffffu, o, 2);

            if (kseg == 0) {
                float gt = sga[s * 64 + vloc];
                float sg = gt / (1.f + expf(-gt));
                out[((blb + t0 + s) * NH + h) * HV + vbase + vloc] = o * sg;
            }
        }
    }
}

// ---------------------------------------------------------------------------
// launch
// ---------------------------------------------------------------------------
extern "C" void kernel_launch(void* const* d_in, const int* in_sizes, int n_in,
                              void* d_out, int out_size)
{
    const float* hidden  = (const float*)d_in[0];  // [2,2048,2048]
    const float* W_qkvgba= (const float*)d_in[1];  // [2048,12320]
    const float* W_conv  = (const float*)d_in[2];  // [8192,4]
    const float* A_log   = (const float*)d_in[3];  // [16]
    const float* dt_bias = (const float*)d_in[4];  // [16]
    float* out = (float*)d_out;                    // [2,2048,16,256]

    // K1: projection GEMM
    {
        dim3 grid((GN + 127) / 128, GM / 128);
        gemm_kernel<<<grid, 256>>>(hidden, W_qkvgba);
    }
    // K2: conv + SiLU
    {
        int tot = B_SZ * L_SEQ * CQKV;
        conv_kernel<<<(tot + 255) / 256, 256>>>(W_conv);
    }
    // K3: l2norm q/k
    {
        int warps = B_SZ * L_SEQ * NH;                 // 65536
        norm_kernel<<<warps * 32 / 256, 256>>>();
    }
    // K4: decay/beta
    {
        int tot = B_SZ * L_SEQ * NH;
        gb_kernel<<<(tot + 255) / 256, 256>>>(A_log, dt_bias);
    }
    // K5: scan
    {
        size_t smem_bytes = (size_t)(2 * CHUNK * SK_ROW + 2 * CHUNK * 64 + 2 * CHUNK) * sizeof(float);
        cudaFuncSetAttribute(scan_kernel, cudaFuncAttributeMaxDynamicSharedMemorySize,
                             (int)smem_bytes);
        scan_kernel<<<128, 256, smem_bytes>>>(out);
    }
}

// round 2
// speedup vs baseline: 2.5137x; 2.5137x over previous
#include <cuda_runtime.h>
#include <cuda_bf16.h>
#include <math.h>
#include <stdint.h>

// ---------------------------------------------------------------------------
// MixerGatedDeltaNet: tf32 tensor-core proj GEMM -> causal depthwise conv4 +
// SiLU -> l2norm -> gated delta-rule scan -> output gate.
// B=2, L=2048, D_MODEL=2048, N_HEADS=16, D_HEAD=128, HEAD_V=256
// ---------------------------------------------------------------------------

#define B_SZ   2
#define L_SEQ  2048
#define DM     2048
#define NPROJ  12320          // q(2048) k(2048) v(4096) gate(4096) b(16) A(16)
#define CQKV   8192
#define NH     16
#define DH     128
#define HV     256
#define KEYD   2048
#define GM     4096           // B*L
#define GK     2048
#define GN     12320

// Scratch (device globals: allocation-free rule)
static __device__ float g_proj[B_SZ * L_SEQ * NPROJ];   // 202 MB
static __device__ float g_qkv [B_SZ * L_SEQ * CQKV];    // 134 MB
static __device__ float g_dec [B_SZ * L_SEQ * NH];
static __device__ float g_beta[B_SZ * L_SEQ * NH];

// ---------------------------------------------------------------------------
// K1: tf32 tensor-core GEMM  g_proj[4096,12320] = hidden[4096,2048] @ W[2048,12320]
// 128x128x32 CTA tile, 8 warps (4x2), warp tile 32x64, mma.m16n8k8 tf32.
// cp.async double buffering. As[m][k] stride 36, Bs[k][n] stride 136.
// ---------------------------------------------------------------------------
#define BM 128
#define BN 128
#define BK 32
#define ASTR 36
#define BSTR 136
#define STAGE_F (BM * ASTR + BK * BSTR)   // floats per stage = 4608 + 4352 = 8960

__device__ __forceinline__ uint32_t f2tf32(float x) {
    uint32_t r;
    asm("cvt.rna.tf32.f32 %0, %1;" : "=r"(r) : "f"(x));
    return r;
}

__device__ __forceinline__ void cpasync16(uint32_t dst_smem, const void* src, int src_bytes) {
    asm volatile("cp.async.cg.shared.global [%0], [%1], 16, %2;"
                 :: "r"(dst_smem), "l"(src), "r"(src_bytes));
}
__device__ __forceinline__ void cpasync_commit() {
    asm volatile("cp.async.commit_group;");
}
template <int N>
__device__ __forceinline__ void cpasync_wait() {
    asm volatile("cp.async.wait_group %0;" :: "n"(N));
}

__device__ __forceinline__ void mma_tf32(float* d,
                                         uint32_t a0, uint32_t a1, uint32_t a2, uint32_t a3,
                                         uint32_t b0, uint32_t b1) {
    asm volatile(
        "mma.sync.aligned.m16n8k8.row.col.f32.tf32.tf32.f32 "
        "{%0,%1,%2,%3}, {%4,%5,%6,%7}, {%8,%9}, {%0,%1,%2,%3};"
        : "+f"(d[0]), "+f"(d[1]), "+f"(d[2]), "+f"(d[3])
        : "r"(a0), "r"(a1), "r"(a2), "r"(a3), "r"(b0), "r"(b1));
}

__global__ __launch_bounds__(256, 2) void gemm_tf32_kernel(const float* __restrict__ A,
                                                           const float* __restrict__ Bm)
{
    extern __shared__ float smem[];

    const int tid = threadIdx.x;
    const int wid = tid >> 5;
    const int lane = tid & 31;
    const int g   = lane >> 2;     // groupID 0..7
    const int tig = lane & 3;      // thread-in-group 0..3

    const int bx = blockIdx.x;     // N tile
    const int by = blockIdx.y;     // M tile
    const int warp_m = (wid & 3) * 32;
    const int warp_n = (wid >> 2) * 64;
    const int rowBase = by * BM;
    const int colBase = bx * BN;

    // cp.async source/dst coordinates (per thread: 4 f4 for A, 4 f4 for B)
    const int aRow  = tid >> 1;              // 0..127 (2 f4 per row... no: 8 f4/row)
    // A tile: 128 rows x 8 float4 = 1024 f4; thread handles c = tid + 256*i
    // B tile: 32 rows x 32 float4 = 1024 f4

    float acc[2][8][4];
#pragma unroll
    for (int mt = 0; mt < 2; mt++)
#pragma unroll
        for (int nt = 0; nt < 8; nt++)
#pragma unroll
            for (int c = 0; c < 4; c++) acc[mt][nt][c] = 0.f;

    uint32_t smem_u32;
    {
        uint64_t tmp;
        asm("{ .reg .u64 t; cvta.to.shared.u64 t, %1; mov.u64 %0, t; }" : "=l"(tmp) : "l"(smem));
        smem_u32 = (uint32_t)tmp;
    }

    const int NIT = GK / BK;   // 64

    // tile loader: stage s (0/1), k-offset k0
    auto loadTile = [&](int k0, int s) {
        float* As = smem + s * STAGE_F;
        float* Bs = As + BM * ASTR;
        uint32_t asb = smem_u32 + (uint32_t)(s * STAGE_F) * 4u;
        uint32_t bsb = asb + BM * ASTR * 4u;
#pragma unroll
        for (int i = 0; i < 4; i++) {
            int c = tid + 256 * i;
            int r = c >> 3, cf = c & 7;
            uint32_t dst = asb + (uint32_t)(r * ASTR + cf * 4) * 4u;
            const float* src = A + (size_t)(rowBase + r) * GK + k0 + cf * 4;
            cpasync16(dst, src, 16);
        }
#pragma unroll
        for (int i = 0; i < 4; i++) {
            int c = tid + 256 * i;
            int r = c >> 5, cf = c & 31;
            int gc = colBase + cf * 4;
            uint32_t dst = bsb + (uint32_t)(r * BSTR + cf * 4) * 4u;
            int ok = (gc < GN);
            const float* src = Bm + (size_t)(k0 + r) * GN + (ok ? gc : 0);
            cpasync16(dst, src, ok ? 16 : 0);
        }
        (void)As; (void)Bs;
    };

    loadTile(0, 0);
    cpasync_commit();

    int buf = 0;
    for (int it = 0; it < NIT; ++it) {
        if (it + 1 < NIT) {
            loadTile((it + 1) * BK, buf ^ 1);
            cpasync_commit();
            cpasync_wait<1>();
        } else {
            cpasync_wait<0>();
        }
        __syncthreads();

        const float* As = smem + buf * STAGE_F;
        const float* Bs = As + BM * ASTR;

#pragma unroll
        for (int ks = 0; ks < 4; ks++) {
            const int kb = ks * 8;
            uint32_t af[2][4];
#pragma unroll
            for (int mt = 0; mt < 2; mt++) {
                int m0 = warp_m + mt * 16 + g;
                af[mt][0] = f2tf32(As[m0 * ASTR + kb + tig]);
                af[mt][1] = f2tf32(As[(m0 + 8) * ASTR + kb + tig]);
                af[mt][2] = f2tf32(As[m0 * ASTR + kb + tig + 4]);
                af[mt][3] = f2tf32(As[(m0 + 8) * ASTR + kb + tig + 4]);
            }
#pragma unroll
            for (int nt = 0; nt < 8; nt++) {
                int n0 = warp_n + nt * 8 + g;
                uint32_t b0 = f2tf32(Bs[(kb + tig) * BSTR + n0]);
                uint32_t b1 = f2tf32(Bs[(kb + tig + 4) * BSTR + n0]);
                mma_tf32(acc[0][nt], af[0][0], af[0][1], af[0][2], af[0][3], b0, b1);
                mma_tf32(acc[1][nt], af[1][0], af[1][1], af[1][2], af[1][3], b0, b1);
            }
        }
        __syncthreads();
        buf ^= 1;
    }

    // epilogue: c0/c1 -> (row, col..col+1), c2/c3 -> (row+8, ..)
#pragma unroll
    for (int mt = 0; mt < 2; mt++) {
        int row = rowBase + warp_m + mt * 16 + g;
#pragma unroll
        for (int nt = 0; nt < 8; nt++) {
            int col = colBase + warp_n + nt * 8 + tig * 2;
            if (col < GN) {
                float2 v0 = make_float2(acc[mt][nt][0], acc[mt][nt][1]);
                float2 v1 = make_float2(acc[mt][nt][2], acc[mt][nt][3]);
                *(float2*)(g_proj + (size_t)row * GN + col) = v0;
                *(float2*)(g_proj + (size_t)(row + 8) * GN + col) = v1;
            }
        }
    }
}

// ---------------------------------------------------------------------------
// K2: causal depthwise conv (width 4) + SiLU over first 8192 proj channels.
// ---------------------------------------------------------------------------
__global__ __launch_bounds__(256) void conv_kernel(const float* __restrict__ Wc)
{
    int idx = blockIdx.x * 256 + threadIdx.x;
    if (idx >= B_SZ * L_SEQ * CQKV) return;
    int c  = idx & (CQKV - 1);
    int bl = idx >> 13;
    int l  = bl & (L_SEQ - 1);

    const float* w = Wc + c * 4;
    float acc = 0.f;
#pragma unroll
    for (int j = 0; j < 4; j++) {
        int lp = l - 3 + j;
        if (lp >= 0) acc += g_proj[(size_t)(bl - 3 + j) * NPROJ + c] * w[j];
    }
    acc = acc / (1.f + expf(-acc));    // SiLU
    g_qkv[idx] = acc;
}

// ---------------------------------------------------------------------------
// K3: l2norm q (scale folded) and k, per (b,l,h). One warp each.
// ---------------------------------------------------------------------------
__global__ __launch_bounds__(256) void norm_kernel()
{
    int gw   = (blockIdx.x * 256 + threadIdx.x) >> 5;
    int lane = threadIdx.x & 31;
    int h  = gw & (NH - 1);
    int bl = gw >> 4;

    float* qp = g_qkv + (size_t)bl * CQKV + h * DH;
    float* kp = qp + KEYD;

    float4 q4 = ((float4*)qp)[lane];
    float4 k4 = ((float4*)kp)[lane];
    float sq = q4.x * q4.x + q4.y * q4.y + q4.z * q4.z + q4.w * q4.w;
    float sk = k4.x * k4.x + k4.y * k4.y + k4.z * k4.z + k4.w * k4.w;
#pragma unroll
    for (int m = 16; m; m >>= 1) {
        sq += __shfl_xor_sync(0xffffffffu, sq, m);
        sk += __shfl_xor_sync(0xffffffffu, sk, m);
    }
    float rq = rsqrtf(sq + 1e-6f) * 0.08838834764831845f;  // * D_HEAD^-0.5
    float rk = rsqrtf(sk + 1e-6f);
    q4.x *= rq; q4.y *= rq; q4.z *= rq; q4.w *= rq;
    k4.x *= rk; k4.y *= rk; k4.z *= rk; k4.w *= rk;
    ((float4*)qp)[lane] = q4;
    ((float4*)kp)[lane] = k4;
}

// ---------------------------------------------------------------------------
// K4: decay/beta prep per (b,l,h).
// ---------------------------------------------------------------------------
__global__ __launch_bounds__(256) void gb_kernel(const float* __restrict__ A_log,
                                                 const float* __restrict__ dt_bias)
{
    int idx = blockIdx.x * 256 + threadIdx.x;
    if (idx >= B_SZ * L_SEQ * NH) return;
    int h  = idx & (NH - 1);
    int bl = idx >> 4;
    const float* pr = g_proj + (size_t)bl * NPROJ;
    float bv = pr[12288 + h];
    float av = pr[12304 + h];
    float beta = 1.f / (1.f + expf(-bv));
    float x  = av + dt_bias[h];
    float sp = (x > 20.f) ? x : log1pf(expf(x));
    float gg = -expf(A_log[h]) * sp;
    g_dec[idx]  = expf(gg);
    g_beta[idx] = beta;
}

// ---------------------------------------------------------------------------
// K5: gated delta-rule scan. grid = 32 (b,h) x 4 v-blocks = 128 CTAs.
// ---------------------------------------------------------------------------
#define CHUNK 64
#define SK_ROW 144

__global__ __launch_bounds__(256) void scan_kernel(float* __restrict__ out)
{
    extern __shared__ float smem[];
    float* sk    = smem;
    float* sq    = sk + CHUNK * SK_ROW;
    float* sv    = sq + CHUNK * SK_ROW;
    float* sga   = sv + CHUNK * 64;
    float* sdec  = sga + CHUNK * 64;
    float* sbeta = sdec + CHUNK;

    const int tid   = threadIdx.x;
    const int vblk  = blockIdx.x & 3;
    const int bh    = blockIdx.x >> 2;
    const int b     = bh >> 4;
    const int h     = bh & 15;
    const int kseg  = tid & 3;
    const int vloc  = tid >> 2;
    const int vbase = vblk * 64;
    const int blb   = b * L_SEQ;

    float S[32];
#pragma unroll
    for (int i = 0; i < 32; i++) S[i] = 0.f;

    for (int t0 = 0; t0 < L_SEQ; t0 += CHUNK) {
        __syncthreads();
        for (int j = tid; j < CHUNK * DH; j += 256) {
            int s = j >> 7, d = j & 127;
            size_t row = (size_t)(blb + t0 + s) * CQKV + h * DH;
            int si  = s * SK_ROW + (d >> 5) * 36 + (d & 31);
            sq[si] = g_qkv[row + d];
            sk[si] = g_qkv[row + KEYD + d];
        }
        for (int j = tid; j < CHUNK * 64; j += 256) {
            int s = j >> 6, v = j & 63;
            int bl = blb + t0 + s;
            sv[j]  = g_qkv[(size_t)bl * CQKV + 2 * KEYD + h * HV + vbase + v];
            sga[j] = g_proj[(size_t)bl * NPROJ + CQKV + h * HV + vbase + v];
        }
        if (tid < CHUNK) {
            int bl = blb + t0 + tid;
            sdec[tid]  = g_dec[bl * NH + h];
            sbeta[tid] = g_beta[bl * NH + h];
        }
        __syncthreads();

        for (int s = 0; s < CHUNK; s++) {
            const float4* kp = (const float4*)&sk[s * SK_ROW + kseg * 36];
            const float4* qp = (const float4*)&sq[s * SK_ROW + kseg * 36];
            float kr[32], qr[32];
#pragma unroll
            for (int i = 0; i < 8; i++) {
                float4 t4 = kp[i];
                kr[4*i+0] = t4.x; kr[4*i+1] = t4.y; kr[4*i+2] = t4.z; kr[4*i+3] = t4.w;
                float4 u4 = qp[i];
                qr[4*i+0] = u4.x; qr[4*i+1] = u4.y; qr[4*i+2] = u4.z; qr[4*i+3] = u4.w;
            }
            float dec  = sdec[s];
            float beta = sbeta[s];

            float kv0 = 0.f, kv1 = 0.f, kv2 = 0.f, kv3 = 0.f;
#pragma unroll
            for (int i = 0; i < 32; i += 4) {
                S[i+0] *= dec; kv0 += kr[i+0] * S[i+0];
                S[i+1] *= dec; kv1 += kr[i+1] * S[i+1];
                S[i+2] *= dec; kv2 += kr[i+2] * S[i+2];
                S[i+3] *= dec; kv3 += kr[i+3] * S[i+3];
            }
            float kv = (kv0 + kv1) + (kv2 + kv3);
            kv += __shfl_xor_sync(0xffffffffu, kv, 1);
            kv += __shfl_xor_sync(0xffffffffu, kv, 2);

            float delta = (sv[s * 64 + vloc] - kv) * beta;

            float o0 = 0.f, o1 = 0.f, o2 = 0.f, o3 = 0.f;
#pragma unroll
            for (int i = 0; i < 32; i += 4) {
                S[i+0] += kr[i+0] * delta; o0 += qr[i+0] * S[i+0];
                S[i+1] += kr[i+1] * delta; o1 += qr[i+1] * S[i+1];
                S[i+2] += kr[i+2] * delta; o2 += qr[i+2] * S[i+2];
                S[i+3] += kr[i+3] * delta; o3 += qr[i+3] * S[i+3];
            }
            float o = (o0 + o1) + (o2 + o3);
            o += __shfl_xor_sync(0xffffffffu, o, 1);
            o += __shfl_xor_sync(0xffffffffu, o, 2);

            if (kseg == 0) {
                float gt = sga[s * 64 + vloc];
                float sg = gt / (1.f + expf(-gt));
                out[((size_t)(blb + t0 + s) * NH + h) * HV + vbase + vloc] = o * sg;
            }
        }
    }
}

// ---------------------------------------------------------------------------
// launch
// ---------------------------------------------------------------------------
extern "C" void kernel_launch(void* const* d_in, const int* in_sizes, int n_in,
                              void* d_out, int out_size)
{
    const float* hidden   = (const float*)d_in[0];
    const float* W_qkvgba = (const float*)d_in[1];
    const float* W_conv   = (const float*)d_in[2];
    const float* A_log    = (const float*)d_in[3];
    const float* dt_bias  = (const float*)d_in[4];
    float* out = (float*)d_out;

    // K1: tf32 tensor-core projection GEMM
    {
        size_t smem_bytes = (size_t)(2 * STAGE_F) * sizeof(float);   // 71680
        cudaFuncSetAttribute(gemm_tf32_kernel,
                             cudaFuncAttributeMaxDynamicSharedMemorySize, (int)smem_bytes);
        dim3 grid((GN + BN - 1) / BN, GM / BM);    // 97 x 32
        gemm_tf32_kernel<<<grid, 256, smem_bytes>>>(hidden, W_qkvgba);
    }
    // K2: conv + SiLU
    {
        int tot = B_SZ * L_SEQ * CQKV;
        conv_kernel<<<(tot + 255) / 256, 256>>>(W_conv);
    }
    // K3: l2norm q/k
    {
        int warps = B_SZ * L_SEQ * NH;
        norm_kernel<<<warps * 32 / 256, 256>>>();
    }
    // K4: decay/beta
    {
        int tot = B_SZ * L_SEQ * NH;
        gb_kernel<<<(tot + 255) / 256, 256>>>(A_log, dt_bias);
    }
    // K5: scan
    {
        size_t smem_bytes = (size_t)(2 * CHUNK * SK_ROW + 2 * CHUNK * 64 + 2 * CHUNK) * sizeof(float);
        cudaFuncSetAttribute(scan_kernel, cudaFuncAttributeMaxDynamicSharedMemorySize,
                             (int)smem_bytes);
        scan_kernel<<<128, 256, smem_bytes>>>(out);
    }
}

// round 3
// speedup vs baseline: 2.8445x; 1.1316x over previous
#include <cuda_runtime.h>
#include <cuda_bf16.h>
#include <math.h>
#include <stdint.h>

// ---------------------------------------------------------------------------
// MixerGatedDeltaNet: tf32 tensor-core proj GEMM (pre-rounded operands) ->
// fused causal conv4+SiLU+l2norm -> gated delta-rule scan -> output gate.
// B=2, L=2048, D_MODEL=2048, N_HEADS=16, D_HEAD=128, HEAD_V=256
// ---------------------------------------------------------------------------

#define B_SZ   2
#define L_SEQ  2048
#define DM     2048
#define NPROJ  12320          // q(2048) k(2048) v(4096) gate(4096) b(16) A(16)
#define CQKV   8192
#define NH     16
#define DH     128
#define HV     256
#define KEYD   2048
#define GM     4096           // B*L
#define GK     2048
#define GN     12320

// Scratch (device globals: allocation-free rule)
static __device__ float g_proj [B_SZ * L_SEQ * NPROJ];   // 202 MB
static __device__ float g_qkv  [B_SZ * L_SEQ * CQKV];    // 134 MB
static __device__ float g_dec  [B_SZ * L_SEQ * NH];
static __device__ float g_beta [B_SZ * L_SEQ * NH];
static __device__ float g_hid_t[GM * GK];                // tf32-rounded hidden
static __device__ float g_w_t  [GK * GN];                // tf32-rounded W

// ---------------------------------------------------------------------------
// K0: round fp32 -> tf32 bit pattern (cvt.rna), elementwise, float4.
// ---------------------------------------------------------------------------
__device__ __forceinline__ float round_tf32(float x) {
    uint32_t r;
    asm("cvt.rna.tf32.f32 %0, %1;" : "=r"(r) : "f"(x));
    return __uint_as_float(r);
}

__global__ __launch_bounds__(256) void round_kernel(const float* __restrict__ src,
                                                    float* __restrict__ dst, int n4)
{
    int i = blockIdx.x * 256 + threadIdx.x;
    if (i >= n4) return;
    float4 v = ((const float4*)src)[i];
    v.x = round_tf32(v.x); v.y = round_tf32(v.y);
    v.z = round_tf32(v.z); v.w = round_tf32(v.w);
    ((float4*)dst)[i] = v;
}

// ---------------------------------------------------------------------------
// K1: tf32 tensor-core GEMM  g_proj[4096,12320] = hid[4096,2048] @ W[2048,12320]
// 128x128x32 CTA tile, 8 warps (4x2), warp tile 32x64, mma.m16n8k8 tf32.
// 3-stage cp.async ring. Operands pre-rounded: no cvt in the hot loop.
// ---------------------------------------------------------------------------
#define BM 128
#define BN 128
#define BK 32
#define ASTR 36
#define BSTR 136
#define STAGE_F (BM * ASTR + BK * BSTR)   // 8960 floats per stage

__device__ __forceinline__ void cpasync16(uint32_t dst_smem, const void* src, int src_bytes) {
    asm volatile("cp.async.cg.shared.global [%0], [%1], 16, %2;"
                 :: "r"(dst_smem), "l"(src), "r"(src_bytes));
}
__device__ __forceinline__ void cpasync_commit() {
    asm volatile("cp.async.commit_group;");
}
template <int N>
__device__ __forceinline__ void cpasync_wait() {
    asm volatile("cp.async.wait_group %0;" :: "n"(N));
}

__device__ __forceinline__ void mma_tf32(float* d,
                                         uint32_t a0, uint32_t a1, uint32_t a2, uint32_t a3,
                                         uint32_t b0, uint32_t b1) {
    asm volatile(
        "mma.sync.aligned.m16n8k8.row.col.f32.tf32.tf32.f32 "
        "{%0,%1,%2,%3}, {%4,%5,%6,%7}, {%8,%9}, {%0,%1,%2,%3};"
        : "+f"(d[0]), "+f"(d[1]), "+f"(d[2]), "+f"(d[3])
        : "r"(a0), "r"(a1), "r"(a2), "r"(a3), "r"(b0), "r"(b1));
}

__global__ __launch_bounds__(256, 2) void gemm_tf32_kernel(const float* __restrict__ A,
                                                           const float* __restrict__ Bm)
{
    extern __shared__ float smem[];

    const int tid  = threadIdx.x;
    const int wid  = tid >> 5;
    const int lane = tid & 31;
    const int g    = lane >> 2;
    const int tig  = lane & 3;

    const int bx = blockIdx.x;
    const int by = blockIdx.y;
    const int warp_m = (wid & 3) * 32;
    const int warp_n = (wid >> 2) * 64;
    const int rowBase = by * BM;
    const int colBase = bx * BN;

    float acc[2][8][4];
#pragma unroll
    for (int mt = 0; mt < 2; mt++)
#pragma unroll
        for (int nt = 0; nt < 8; nt++)
#pragma unroll
            for (int c = 0; c < 4; c++) acc[mt][nt][c] = 0.f;

    uint32_t smem_u32;
    {
        uint64_t tmp;
        asm("{ .reg .u64 t; cvta.to.shared.u64 t, %1; mov.u64 %0, t; }" : "=l"(tmp) : "l"(smem));
        smem_u32 = (uint32_t)tmp;
    }

    const int NIT = GK / BK;   // 64

    auto loadTile = [&](int k0, int s) {
        uint32_t asb = smem_u32 + (uint32_t)(s * STAGE_F) * 4u;
        uint32_t bsb = asb + BM * ASTR * 4u;
#pragma unroll
        for (int i = 0; i < 4; i++) {
            int c = tid + 256 * i;
            int r = c >> 3, cf = c & 7;
            uint32_t dst = asb + (uint32_t)(r * ASTR + cf * 4) * 4u;
            const float* src = A + (size_t)(rowBase + r) * GK + k0 + cf * 4;
            cpasync16(dst, src, 16);
        }
#pragma unroll
        for (int i = 0; i < 4; i++) {
            int c = tid + 256 * i;
            int r = c >> 5, cf = c & 31;
            int gc = colBase + cf * 4;
            uint32_t dst = bsb + (uint32_t)(r * BSTR + cf * 4) * 4u;
            int ok = (gc < GN);
            const float* src = Bm + (size_t)(k0 + r) * GN + (ok ? gc : 0);
            cpasync16(dst, src, ok ? 16 : 0);
        }
    };

    loadTile(0, 0);      cpasync_commit();
    loadTile(BK, 1);     cpasync_commit();

    int buf = 0;
    for (int it = 0; it < NIT; ++it) {
        if (it == NIT - 1) cpasync_wait<0>(); else cpasync_wait<1>();
        __syncthreads();

        const float* As = smem + buf * STAGE_F;
        const float* Bs = As + BM * ASTR;
        const uint32_t* Au = (const uint32_t*)As;
        const uint32_t* Bu = (const uint32_t*)Bs;

#pragma unroll
        for (int ks = 0; ks < 4; ks++) {
            const int kb = ks * 8;
            uint32_t af[2][4];
#pragma unroll
            for (int mt = 0; mt < 2; mt++) {
                int m0 = warp_m + mt * 16 + g;
                af[mt][0] = Au[m0 * ASTR + kb + tig];
                af[mt][1] = Au[(m0 + 8) * ASTR + kb + tig];
                af[mt][2] = Au[m0 * ASTR + kb + tig + 4];
                af[mt][3] = Au[(m0 + 8) * ASTR + kb + tig + 4];
            }
#pragma unroll
            for (int nt = 0; nt < 8; nt++) {
                int n0 = warp_n + nt * 8 + g;
                uint32_t b0 = Bu[(kb + tig) * BSTR + n0];
                uint32_t b1 = Bu[(kb + tig + 4) * BSTR + n0];
                mma_tf32(acc[0][nt], af[0][0], af[0][1], af[0][2], af[0][3], b0, b1);
                mma_tf32(acc[1][nt], af[1][0], af[1][1], af[1][2], af[1][3], b0, b1);
            }
        }

        if (it + 2 < NIT) {
            __syncthreads();
            loadTile((it + 2) * BK, (it + 2) % 3);
            cpasync_commit();
        }
        buf = (buf + 1) % 3;
    }

#pragma unroll
    for (int mt = 0; mt < 2; mt++) {
        int row = rowBase + warp_m + mt * 16 + g;
#pragma unroll
        for (int nt = 0; nt < 8; nt++) {
            int col = colBase + warp_n + nt * 8 + tig * 2;
            if (col < GN) {
                *(float2*)(g_proj + (size_t)row * GN + col) =
                    make_float2(acc[mt][nt][0], acc[mt][nt][1]);
                *(float2*)(g_proj + (size_t)(row + 8) * GN + col) =
                    make_float2(acc[mt][nt][2], acc[mt][nt][3]);
            }
        }
    }
}

// ---------------------------------------------------------------------------
// K2a: fused conv4 + SiLU + l2norm for q,k. One 128-thread block per
// (bl, head-slot). head-slots 0..15 = q heads (scale folded), 16..31 = k heads.
// ---------------------------------------------------------------------------
__global__ __launch_bounds__(128) void conv_qk_norm_kernel(const float* __restrict__ Wc)
{
    const int blk = blockIdx.x;            // 0 .. 4096*32-1
    const int hs  = blk & 31;
    const int bl  = blk >> 5;
    const int tid = threadIdx.x;
    const int c   = hs * 128 + tid;        // channel in [0, 4096)
    const int l   = bl & (L_SEQ - 1);

    const float4 w = *(const float4*)(Wc + c * 4);
    float acc = 0.f;
    {
        const float* base = g_proj + (size_t)bl * NPROJ + c;
        if (l >= 3) {
            acc = base[-3 * NPROJ] * w.x + base[-2 * NPROJ] * w.y +
                  base[-1 * NPROJ] * w.z + base[0] * w.w;
        } else {
            if (l >= 3) acc += base[-3 * NPROJ] * w.x;
            if (l >= 2) acc += base[-2 * NPROJ] * w.y;
            if (l >= 1) acc += base[-1 * NPROJ] * w.z;
            acc += base[0] * w.w;
        }
    }
    acc = acc / (1.f + expf(-acc));        // SiLU

    // block l2norm over 128 channels
    __shared__ float part[4];
    float s = acc * acc;
#pragma unroll
    for (int m = 16; m; m >>= 1) s += __shfl_xor_sync(0xffffffffu, s, m);
    if ((tid & 31) == 0) part[tid >> 5] = s;
    __syncthreads();
    float sum = part[0] + part[1] + part[2] + part[3];
    float r = rsqrtf(sum + 1e-6f);
    if (hs < 16) r *= 0.08838834764831845f;   // fold D_HEAD^-0.5 into q

    g_qkv[(size_t)bl * CQKV + c] = acc * r;
}

// ---------------------------------------------------------------------------
// K2b: conv4 + SiLU for v channels [4096, 8192).
// ---------------------------------------------------------------------------
__global__ __launch_bounds__(256) void conv_v_kernel(const float* __restrict__ Wc)
{
    int idx = blockIdx.x * 256 + threadIdx.x;      // over 4096*4096
    if (idx >= GM * 4096) return;
    int cv = idx & 4095;
    int bl = idx >> 12;
    int c  = 4096 + cv;
    int l  = bl & (L_SEQ - 1);

    const float4 w = *(const float4*)(Wc + c * 4);
    const float* base = g_proj + (size_t)bl * NPROJ + c;
    float acc = base[0] * w.w;
    if (l >= 1) acc += base[-1 * NPROJ] * w.z;
    if (l >= 2) acc += base[-2 * NPROJ] * w.y;
    if (l >= 3) acc += base[-3 * NPROJ] * w.x;
    acc = acc / (1.f + expf(-acc));
    g_qkv[(size_t)bl * CQKV + c] = acc;
}

// ---------------------------------------------------------------------------
// K4: decay/beta prep per (b,l,h).
// ---------------------------------------------------------------------------
__global__ __launch_bounds__(256) void gb_kernel(const float* __restrict__ A_log,
                                                 const float* __restrict__ dt_bias)
{
    int idx = blockIdx.x * 256 + threadIdx.x;
    if (idx >= B_SZ * L_SEQ * NH) return;
    int h  = idx & (NH - 1);
    int bl = idx >> 4;
    const float* pr = g_proj + (size_t)bl * NPROJ;
    float bv = pr[12288 + h];
    float av = pr[12304 + h];
    float beta = 1.f / (1.f + expf(-bv));
    float x  = av + dt_bias[h];
    float sp = (x > 20.f) ? x : log1pf(expf(x));
    float gg = -expf(A_log[h]) * sp;
    g_dec[idx]  = expf(gg);
    g_beta[idx] = beta;
}

// ---------------------------------------------------------------------------
// K5: gated delta-rule scan. grid = 32 (b,h) x 4 v-blocks = 128 CTAs.
// 256 threads; thread (kseg = tid&3, vloc = tid>>2) owns S[kseg*32..+31, vloc].
// ---------------------------------------------------------------------------
#define CHUNK 64
#define SK_ROW 144

__global__ __launch_bounds__(256) void scan_kernel(float* __restrict__ out)
{
    extern __shared__ float smem[];
    float* sk    = smem;
    float* sq    = sk + CHUNK * SK_ROW;
    float* sv    = sq + CHUNK * SK_ROW;
    float* sga   = sv + CHUNK * 64;
    float* sdec  = sga + CHUNK * 64;
    float* sbeta = sdec + CHUNK;

    const int tid   = threadIdx.x;
    const int vblk  = blockIdx.x & 3;
    const int bh    = blockIdx.x >> 2;
    const int b     = bh >> 4;
    const int h     = bh & 15;
    const int kseg  = tid & 3;
    const int vloc  = tid >> 2;
    const int vbase = vblk * 64;
    const int blb   = b * L_SEQ;

    float S[32];
#pragma unroll
    for (int i = 0; i < 32; i++) S[i] = 0.f;

    for (int t0 = 0; t0 < L_SEQ; t0 += CHUNK) {
        __syncthreads();
        // stage q,k via float4 (seg-padded layout)
        for (int j = tid; j < CHUNK * DH / 4; j += 256) {
            int s = j >> 5, d = (j & 31) * 4;
            size_t row = (size_t)(blb + t0 + s) * CQKV + h * DH;
            int si = s * SK_ROW + (d >> 5) * 36 + (d & 31);
            *(float4*)&sq[si] = *(const float4*)&g_qkv[row + d];
            *(float4*)&sk[si] = *(const float4*)&g_qkv[row + KEYD + d];
        }
        for (int j = tid; j < CHUNK * 64 / 4; j += 256) {
            int s = j >> 4, v = (j & 15) * 4;
            int bl = blb + t0 + s;
            *(float4*)&sv[s * 64 + v] =
                *(const float4*)&g_qkv[(size_t)bl * CQKV + 2 * KEYD + h * HV + vbase + v];
            *(float4*)&sga[s * 64 + v] =
                *(const float4*)&g_proj[(size_t)bl * NPROJ + CQKV + h * HV + vbase + v];
        }
        if (tid < CHUNK) {
            int bl = blb + t0 + tid;
            sdec[tid]  = g_dec[bl * NH + h];
            sbeta[tid] = g_beta[bl * NH + h];
        }
        __syncthreads();

#pragma unroll 2
        for (int s = 0; s < CHUNK; s++) {
            const float4* kp = (const float4*)&sk[s * SK_ROW + kseg * 36];
            const float4* qp = (const float4*)&sq[s * SK_ROW + kseg * 36];
            float kr[32], qr[32];
#pragma unroll
            for (int i = 0; i < 8; i++) {
                float4 t4 = kp[i];
                kr[4*i+0] = t4.x; kr[4*i+1] = t4.y; kr[4*i+2] = t4.z; kr[4*i+3] = t4.w;
                float4 u4 = qp[i];
                qr[4*i+0] = u4.x; qr[4*i+1] = u4.y; qr[4*i+2] = u4.z; qr[4*i+3] = u4.w;
            }
            float dec  = sdec[s];
            float beta = sbeta[s];

            float kv0 = 0.f, kv1 = 0.f, kv2 = 0.f, kv3 = 0.f;
#pragma unroll
            for (int i = 0; i < 32; i += 4) {
                S[i+0] *= dec; kv0 += kr[i+0] * S[i+0];
                S[i+1] *= dec; kv1 += kr[i+1] * S[i+1];
                S[i+2] *= dec; kv2 += kr[i+2] * S[i+2];
                S[i+3] *= dec; kv3 += kr[i+3] * S[i+3];
            }
            float kv = (kv0 + kv1) + (kv2 + kv3);
            kv += __shfl_xor_sync(0xffffffffu, kv, 1);
            kv += __shfl_xor_sync(0xffffffffu, kv, 2);

            float delta = (sv[s * 64 + vloc] - kv) * beta;

            float o0 = 0.f, o1 = 0.f, o2 = 0.f, o3 = 0.f;
#pragma unroll
            for (int i = 0; i < 32; i += 4) {
                S[i+0] += kr[i+0] * delta; o0 += qr[i+0] * S[i+0];
                S[i+1] += kr[i+1] * delta; o1 += qr[i+1] * S[i+1];
                S[i+2] += kr[i+2] * delta; o2 += qr[i+2] * S[i+2];
                S[i+3] += kr[i+3] * delta; o3 += qr[i+3] * S[i+3];
            }
            float o = (o0 + o1) + (o2 + o3);
            o += __shfl_xor_sync(0xffffffffu, o, 1);
            o += __shfl_xor_sync(0xffffffffu, o, 2);

            if (kseg == 0) {
                float gt = sga[s * 64 + vloc];
                float sg = gt / (1.f + expf(-gt));
                out[((size_t)(blb + t0 + s) * NH + h) * HV + vbase + vloc] = o * sg;
            }
        }
    }
}

// ---------------------------------------------------------------------------
// launch
// ---------------------------------------------------------------------------
extern "C" void kernel_launch(void* const* d_in, const int* in_sizes, int n_in,
                              void* d_out, int out_size)
{
    const float* hidden   = (const float*)d_in[0];
    const float* W_qkvgba = (const float*)d_in[1];
    const float* W_conv   = (const float*)d_in[2];
    const float* A_log    = (const float*)d_in[3];
    const float* dt_bias  = (const float*)d_in[4];
    float* out = (float*)d_out;

    float* hid_t; cudaGetSymbolAddress((void**)&hid_t, g_hid_t);
    float* w_t;   cudaGetSymbolAddress((void**)&w_t,   g_w_t);

    // K0: pre-round operands to tf32 bit patterns
    {
        int n4h = GM * GK / 4;
        round_kernel<<<(n4h + 255) / 256, 256>>>(hidden, hid_t, n4h);
        int n4w = GK * GN / 4;
        round_kernel<<<(n4w + 255) / 256, 256>>>(W_qkvgba, w_t, n4w);
    }
    // K1: tf32 tensor-core projection GEMM (3-stage)
    {
        size_t smem_bytes = (size_t)(3 * STAGE_F) * sizeof(float);   // 107520
        cudaFuncSetAttribute(gemm_tf32_kernel,
                             cudaFuncAttributeMaxDynamicSharedMemorySize, (int)smem_bytes);
        dim3 grid((GN + BN - 1) / BN, GM / BM);    // 97 x 32
        gemm_tf32_kernel<<<grid, 256, smem_bytes>>>(hid_t, w_t);
    }
    // K2a: fused conv+SiLU+l2norm for q,k
    conv_qk_norm_kernel<<<GM * 32, 128>>>(W_conv);
    // K2b: conv+SiLU for v
    {
        int tot = GM * 4096;
        conv_v_kernel<<<(tot + 255) / 256, 256>>>(W_conv);
    }
    // K4: decay/beta
    {
        int tot = B_SZ * L_SEQ * NH;
        gb_kernel<<<(tot + 255) / 256, 256>>>(A_log, dt_bias);
    }
    // K5: scan
    {
        size_t smem_bytes = (size_t)(2 * CHUNK * SK_ROW + 2 * CHUNK * 64 + 2 * CHUNK) * sizeof(float);
        cudaFuncSetAttribute(scan_kernel, cudaFuncAttributeMaxDynamicSharedMemorySize,
                             (int)smem_bytes);
        scan_kernel<<<128, 256, smem_bytes>>>(out);
    }
}